// round 2
// baseline (speedup 1.0000x reference)
#include <cuda_runtime.h>
#include <math.h>

#define NF 64
#define ND 32
#define NPAIR 2016
#define SPF 68                    // floats per f-row: 16 data quads + 1 pad quad
#define PAIR_F (64 * SPF)         // 4352 floats per sample-pair
#define NPAIRS_CTA 8              // sample-pairs per CTA -> 16 samples
#define NTHREADS 288              // 8 pairs * 36 triangle tiles = 288 jobs
#define SMEM_BYTES (NPAIRS_CTA * PAIR_F * 4)   // 139264 B

__device__ __forceinline__ void fma2(unsigned long long &acc,
                                     unsigned long long a,
                                     unsigned long long b) {
    asm("fma.rn.f32x2 %0, %1, %2, %0;" : "+l"(acc) : "l"(a), "l"(b));
}

// smem element layout per pair: addr(f, d, s) = f*SPF + (qp)*4 + (d&1)*2 + s
// where q = d>>1 and qp = q ^ ((f>>3)&7)   (XOR swizzle kills stride-8 conflicts)
__global__ __launch_bounds__(NTHREADS, 1)
void gram_ut_f32x2(const float* __restrict__ in, float* __restrict__ out)
{
    extern __shared__ float sm[];
    const int tid = threadIdx.x;
    const int B = blockIdx.x * 16;           // 16 samples per CTA

    // ---------------- Phase 1: coalesced load + interleave-transpose ----------
    {
        const float4* gsrc = (const float4*)(in + (size_t)B * (NF * ND));
        for (int idx = tid; idx < 16 * 512; idx += NTHREADS) {
            float4 v = gsrc[idx];                 // fully coalesced
            int sl  = idx >> 9;                   // local sample 0..15
            int rem = idx & 511;
            int f   = rem >> 3;                   // field 0..63
            int dq  = rem & 7;                    // d-quad 0..7 (d0 = 4*dq)
            int pr  = sl >> 1;
            int s   = sl & 1;
            float* dp = sm + pr * PAIR_F + f * SPF;
            int key = (f >> 3) & 7;
            int q0 = (2 * dq) ^ key;              // quad for d0,d0+1
            int q1 = (2 * dq + 1) ^ key;          // quad for d0+2,d0+3
            dp[q0 * 4 + 0 + s] = v.x;             // d even, s
            dp[q0 * 4 + 2 + s] = v.y;             // d odd,  s
            dp[q1 * 4 + 0 + s] = v.z;
            dp[q1 * 4 + 2 + s] = v.w;
        }
    }
    __syncthreads();

    // ---------------- Phase 2: triangle-tile dual-sample FMA2 ------------------
    // job = tid: pair pr (0..7), tile t (0..35) over 8x8 tile grid, r<=c
    const int pr = tid / 36;
    const int t  = tid - pr * 36;
    int r = 0, cum = 0;
    while (t >= cum + (8 - r)) { cum += 8 - r; ++r; }
    const int c = r + (t - cum);
    const int i0 = r * 8, j0 = c * 8;

    const float* base = sm + pr * PAIR_F;
    const char* rowp = (const char*)(base + i0 * SPF);
    const char* colp = (const char*)(base + j0 * SPF);

    unsigned long long acc[8][8];
    #pragma unroll
    for (int ii = 0; ii < 8; ++ii)
        #pragma unroll
        for (int jj = 0; jj < 8; ++jj)
            acc[ii][jj] = 0ull;

    #pragma unroll
    for (int d2 = 0; d2 < 16; ++d2) {
        const int rq = (d2 ^ r) << 4;            // byte offset of swizzled quad
        const int cq = (d2 ^ c) << 4;
        ulonglong2 rv[8];
        #pragma unroll
        for (int ii = 0; ii < 8; ++ii)
            rv[ii] = *(const ulonglong2*)(rowp + ii * (SPF * 4) + rq);
        #pragma unroll
        for (int jj = 0; jj < 8; ++jj) {
            ulonglong2 cv = *(const ulonglong2*)(colp + jj * (SPF * 4) + cq);
            #pragma unroll
            for (int ii = 0; ii < 8; ++ii) {
                fma2(acc[ii][jj], rv[ii].x, cv.x);   // dim d
                fma2(acc[ii][jj], rv[ii].y, cv.y);   // dim d+1
            }
        }
    }
    __syncthreads();          // all reads of input smem done; region reusable

    // ---------------- Phase 3+4: two staging waves (4 pairs each) --------------
    float* G = sm;            // reuse: 4 pairs * 64*64*2 floats = 32768 <= 34816
    #pragma unroll 1
    for (int w = 0; w < 2; ++w) {
        if ((pr >> 2) == w) {
            float* Gp = G + (pr & 3) * 8192;
            #pragma unroll
            for (int ii = 0; ii < 8; ++ii) {
                int i = i0 + ii;
                #pragma unroll
                for (int jj = 0; jj < 8; jj += 2) {
                    ulonglong2 st;
                    st.x = acc[ii][jj];
                    st.y = acc[ii][jj + 1];
                    *(ulonglong2*)(Gp + (i * 64 + (j0 + jj)) * 2) = st;
                }
            }
        }
        __syncthreads();

        // copy-out 8 samples of this wave: 8 * 504 output float4s
        for (int o4 = tid; o4 < 8 * 504; o4 += NTHREADS) {
            int s8 = o4 / 504;                   // 0..7
            int p4 = o4 - s8 * 504;
            int p  = p4 * 4;
            int pr3 = s8 >> 1;
            int s   = s8 & 1;
            int b   = B + w * 8 + pr3 * 2 + s;   // global sample
            const float* Gp = G + pr3 * 8192;

            // invert p -> (i,j), i<j over 64 fields (exact discriminant + fixups)
            int i = (int)((127.0f - sqrtf(16129.0f - 8.0f * (float)p)) * 0.5f);
            while (((i + 1) * (126 - i)) >> 1 <= p) ++i;
            while ((i * (127 - i)) >> 1 > p) --i;
            int j = i + 1 + (p - ((i * (127 - i)) >> 1));

            float4 o;
            o.x = Gp[(i * 64 + j) * 2 + s]; if (++j == NF) { ++i; j = i + 1; }
            o.y = Gp[(i * 64 + j) * 2 + s]; if (++j == NF) { ++i; j = i + 1; }
            o.z = Gp[(i * 64 + j) * 2 + s]; if (++j == NF) { ++i; j = i + 1; }
            o.w = Gp[(i * 64 + j) * 2 + s];
            *(float4*)(out + (size_t)b * NPAIR + p) = o;
        }
        __syncthreads();
    }
}

extern "C" void kernel_launch(void* const* d_in, const int* in_sizes, int n_in,
                              void* d_out, int out_size)
{
    const float* in  = (const float*)d_in[0];
    float*       out = (float*)d_out;
    int nb = in_sizes[0] / (NF * ND);            // 16384
    cudaFuncSetAttribute(gram_ut_f32x2,
                         cudaFuncAttributeMaxDynamicSharedMemorySize, SMEM_BYTES);
    gram_ut_f32x2<<<nb / 16, NTHREADS, SMEM_BYTES>>>(in, out);
}

// round 3
// speedup vs baseline: 1.3208x; 1.3208x over previous
#include <cuda_runtime.h>
#include <math.h>

#define NF 64
#define ND 32
#define NPAIR 2016
#define SROW 68              // floats per field row: 32 d * 2 samples + 4 pad
#define PAIR_F (NF * SROW)   // 4352 floats per sample-pair
#define GSTRIDE 65           // float2 stride of staged gram rows (conflict-free)

__device__ __forceinline__ void fma2(unsigned long long &acc,
                                     unsigned long long a,
                                     unsigned long long b) {
    asm("fma.rn.f32x2 %0, %1, %2, %0;" : "+l"(acc) : "l"(a), "l"(b));
}

// 128 threads = 2 groups of 64. Group g computes the full 64x64 gram for
// sample pair (4*blk + 2g, 4*blk + 2g + 1) with f32x2 packed math.
// smem element (f, d, s) at  g*PAIR_F + f*SROW + d*2 + s  ->
// one float4 at (f*SROW + 4*dp) holds dims {2dp, 2dp+1} for both samples.
__global__ __launch_bounds__(128, 1)
void gram_f32x2(const float* __restrict__ in, float* __restrict__ out)
{
    __shared__ float sm[2 * PAIR_F];     // 34816 B, reused for G staging
    const int tid = threadIdx.x;
    const int grp = tid >> 6;
    const int gt  = tid & 63;
    const int B   = blockIdx.x * 4;

    // ---------- Phase 1: coalesced load + sample-interleave transpose ----------
    {
        const float4* gsrc = (const float4*)(in + (size_t)B * (NF * ND));
        #pragma unroll
        for (int k = 0; k < 16; ++k) {
            int idx = tid + k * 128;          // 2048 float4 total (4 samples)
            float4 v = gsrc[idx];
            int sl  = idx >> 9;               // local sample 0..3
            int g   = sl >> 1;
            int s   = sl & 1;
            int rem = idx & 511;
            int f   = rem >> 3;               // field
            int dq  = rem & 7;                // d0 = 4*dq
            float* dp = sm + g * PAIR_F + f * SROW + dq * 8 + s;
            dp[0] = v.x;                      // d = 4dq
            dp[2] = v.y;                      // d = 4dq+1
            dp[4] = v.z;
            dp[6] = v.w;
        }
    }
    __syncthreads();

    // ---------- Phase 2: 8x8 f32x2 register-tile gram ----------
    const int tx = gt & 7;                    // col group: j = tx + 8*jj
    const int ty = gt >> 3;                   // row group: i = ty*8 + ii

    const char* rowp = (const char*)(sm + grp * PAIR_F + (ty * 8) * SROW);
    const char* colp = (const char*)(sm + grp * PAIR_F + tx * SROW);

    unsigned long long acc[8][8];
    #pragma unroll
    for (int ii = 0; ii < 8; ++ii)
        #pragma unroll
        for (int jj = 0; jj < 8; ++jj)
            acc[ii][jj] = 0ull;

    #pragma unroll 4
    for (int dp2 = 0; dp2 < 16; ++dp2) {      // two dims per iter
        const int off = dp2 * 16;             // byte offset of float4 quad
        ulonglong2 rv[8];
        #pragma unroll
        for (int ii = 0; ii < 8; ++ii)
            rv[ii] = *(const ulonglong2*)(rowp + ii * (SROW * 4) + off);
        #pragma unroll
        for (int jj = 0; jj < 8; ++jj) {
            ulonglong2 cv = *(const ulonglong2*)(colp + jj * (8 * SROW * 4) + off);
            #pragma unroll
            for (int ii = 0; ii < 8; ++ii) {
                fma2(acc[ii][jj], rv[ii].x, cv.x);   // dim 2*dp2
                fma2(acc[ii][jj], rv[ii].y, cv.y);   // dim 2*dp2+1
            }
        }
    }
    __syncthreads();      // all A reads done; smem reusable for G staging

    // ---------- Phase 3+4: two staging waves (one pair each) ----------
    float2* G = (float2*)sm;                  // 64 x GSTRIDE float2 = 33280 B
    #pragma unroll 1
    for (int w = 0; w < 2; ++w) {
        if (grp == w) {
            #pragma unroll
            for (int ii = 0; ii < 8; ++ii) {
                int i = ty * 8 + ii;
                #pragma unroll
                for (int jj = 0; jj < 8; ++jj) {
                    int j = tx + 8 * jj;
                    *(unsigned long long*)&G[i * GSTRIDE + j] = acc[ii][jj];
                }
            }
        }
        __syncthreads();

        // copy-out the pair's 2 samples: 2 * 504 float4 quads, coalesced STG
        for (int o4 = tid; o4 < 1008; o4 += 128) {
            int s  = o4 >= 504;
            int p4 = o4 - s * 504;
            int p  = p4 * 4;
            int b  = B + w * 2 + s;

            // invert p -> (i,j), i<j, via exact discriminant + integer fixups
            int i = (int)((127.0f - sqrtf(16129.0f - 8.0f * (float)p)) * 0.5f);
            while (((i + 1) * (126 - i)) >> 1 <= p) ++i;
            while ((i * (127 - i)) >> 1 > p) --i;
            int j = i + 1 + (p - ((i * (127 - i)) >> 1));

            const float* Gs = (const float*)G + s;   // select sample lane
            float4 o;
            o.x = Gs[(i * GSTRIDE + j) * 2]; if (++j == NF) { ++i; j = i + 1; }
            o.y = Gs[(i * GSTRIDE + j) * 2]; if (++j == NF) { ++i; j = i + 1; }
            o.z = Gs[(i * GSTRIDE + j) * 2]; if (++j == NF) { ++i; j = i + 1; }
            o.w = Gs[(i * GSTRIDE + j) * 2];
            *(float4*)(out + (size_t)b * NPAIR + p) = o;
        }
        __syncthreads();
    }
}

extern "C" void kernel_launch(void* const* d_in, const int* in_sizes, int n_in,
                              void* d_out, int out_size)
{
    const float* in  = (const float*)d_in[0];
    float*       out = (float*)d_out;
    int nb = in_sizes[0] / (NF * ND);        // 16384
    gram_f32x2<<<nb / 4, 128>>>(in, out);
}

// round 5
// speedup vs baseline: 2.5509x; 1.9313x over previous
#include <cuda_runtime.h>
#include <cuda_bf16.h>
#include <stdint.h>
#include <math.h>

#define NF 64
#define ND 32
#define NPAIR 2016
#define AROWB 144                  // bytes per field row: 64B hi | 64B lo | 16B pad
#define A_BYTES (2 * 64 * AROWB)   // 18432
#define GSTR 66                    // float stride of staged gram rows
#define SMEM_TOTAL (A_BYTES + 2 * 64 * GSTR * 4)   // 18432 + 33792 = 52224

__device__ __forceinline__ uint32_t s2u(const void* p) {
    return (uint32_t)__cvta_generic_to_shared(p);
}

// One job: sample S, row strip [R0, R0+16), n-tiles t = TMIN..7 (8 cols each).
// acc[t-TMIN][4] accumulates the m16n8 fragment.
template<int S, int R0, int TMIN>
__device__ __forceinline__ void run_job(uint32_t smA, int lane, float acc[][4])
{
    uint32_t pA = smA + (uint32_t)((S * 64 + R0 + (lane & 15)) * AROWB)
                      + (uint32_t)((lane >> 4) << 4);
    uint32_t pB = smA + (uint32_t)((S * 64 + (lane & 7)) * AROWB)
                      + (uint32_t)(((lane >> 3) & 1) << 4);
    #pragma unroll
    for (int pass = 0; pass < 3; ++pass) {          // (hi,hi) (hi,lo) (lo,hi)
        const int aoff = (pass == 2) ? 64 : 0;
        const int boff = (pass == 1) ? 64 : 0;
        #pragma unroll
        for (int kc = 0; kc < 2; ++kc) {            // K=32 as 2 x k16
            uint32_t a0, a1, a2, a3;
            asm volatile("ldmatrix.sync.aligned.m8n8.x4.shared.b16 {%0,%1,%2,%3}, [%4];"
                : "=r"(a0), "=r"(a1), "=r"(a2), "=r"(a3)
                : "r"(pA + aoff + kc * 32));
            #pragma unroll
            for (int t = TMIN; t < 8; ++t) {
                uint32_t b0, b1;
                asm volatile("ldmatrix.sync.aligned.m8n8.x2.shared.b16 {%0,%1}, [%2];"
                    : "=r"(b0), "=r"(b1)
                    : "r"(pB + (uint32_t)(t * 8 * AROWB) + boff + kc * 32));
                float* c = acc[t - TMIN];
                asm volatile(
                    "mma.sync.aligned.m16n8k16.row.col.f32.bf16.bf16.f32 "
                    "{%0,%1,%2,%3}, {%4,%5,%6,%7}, {%8,%9}, {%0,%1,%2,%3};"
                    : "+f"(c[0]), "+f"(c[1]), "+f"(c[2]), "+f"(c[3])
                    : "r"(a0), "r"(a1), "r"(a2), "r"(a3), "r"(b0), "r"(b1));
            }
        }
    }
}

template<int S, int R0, int TMIN>
__device__ __forceinline__ void stage(float* G, int lane, float acc[][4])
{
    float* Gs = G + S * 64 * GSTR;
    const int r  = R0 + (lane >> 2);
    const int cb = 2 * (lane & 3);
    #pragma unroll
    for (int t = TMIN; t < 8; ++t) {
        float* c = acc[t - TMIN];
        int col = 8 * t + cb;
        *(float2*)&Gs[r * GSTR + col]       = make_float2(c[0], c[1]);
        *(float2*)&Gs[(r + 8) * GSTR + col] = make_float2(c[2], c[3]);
    }
}

__global__ __launch_bounds__(128, 4)
void gram_hmma(const float* __restrict__ in, float* __restrict__ out)
{
    extern __shared__ __align__(16) uint8_t smem[];
    float* G = (float*)(smem + A_BYTES);

    const int tid  = threadIdx.x;
    const int w    = tid >> 5;
    const int lane = tid & 31;
    const uint32_t smA = s2u(smem);

    // ---- Phase 1: load 2 samples, split fp32 -> hi/lo bf16, field-major tile
    {
        const float4* src = (const float4*)(in + (size_t)blockIdx.x * 4096);
        #pragma unroll
        for (int k = 0; k < 8; ++k) {
            int idx = tid + k * 128;            // 1024 float4 (2 samples)
            float4 v = src[idx];
            int row = idx >> 3;                 // sample*64 + field
            int dq  = idx & 7;                  // d0 = 4*dq
            uint32_t hA, hB, lA, lB;
            asm("cvt.rn.bf16x2.f32 %0, %1, %2;" : "=r"(hA) : "f"(v.y), "f"(v.x));
            asm("cvt.rn.bf16x2.f32 %0, %1, %2;" : "=r"(hB) : "f"(v.w), "f"(v.z));
            float r0 = v.x - __uint_as_float(hA << 16);
            float r1 = v.y - __uint_as_float(hA & 0xFFFF0000u);
            float r2 = v.z - __uint_as_float(hB << 16);
            float r3 = v.w - __uint_as_float(hB & 0xFFFF0000u);
            asm("cvt.rn.bf16x2.f32 %0, %1, %2;" : "=r"(lA) : "f"(r1), "f"(r0));
            asm("cvt.rn.bf16x2.f32 %0, %1, %2;" : "=r"(lB) : "f"(r3), "f"(r2));
            uint8_t* base = smem + row * AROWB + dq * 8;
            *(uint2*)base        = make_uint2(hA, hB);   // hi: cols 4dq..4dq+3
            *(uint2*)(base + 64) = make_uint2(lA, lB);   // lo
        }
    }
    __syncthreads();

    // ---- Phase 2+3: tensor-core gram (triangle tiles, balanced) + stage to G
    switch (w) {
    case 0: { float a0[8][4]{}, a1[2][4]{};
              run_job<0,  0, 0>(smA, lane, a0); run_job<1, 48, 6>(smA, lane, a1);
              stage  <0,  0, 0>(G, lane, a0);   stage  <1, 48, 6>(G, lane, a1); } break;
    case 1: { float a0[6][4]{}, a1[4][4]{};
              run_job<0, 16, 2>(smA, lane, a0); run_job<1, 32, 4>(smA, lane, a1);
              stage  <0, 16, 2>(G, lane, a0);   stage  <1, 32, 4>(G, lane, a1); } break;
    case 2: { float a0[4][4]{}, a1[6][4]{};
              run_job<0, 32, 4>(smA, lane, a0); run_job<1, 16, 2>(smA, lane, a1);
              stage  <0, 32, 4>(G, lane, a0);   stage  <1, 16, 2>(G, lane, a1); } break;
    default:{ float a0[2][4]{}, a1[8][4]{};
              run_job<0, 48, 6>(smA, lane, a0); run_job<1,  0, 0>(smA, lane, a1);
              stage  <0, 48, 6>(G, lane, a0);   stage  <1,  0, 0>(G, lane, a1); } break;
    }
    __syncthreads();

    // ---- Phase 4: coalesced float4 upper-triangle copy-out (2 samples)
    for (int o = tid; o < 1008; o += 128) {
        int s  = o >= 504;
        int p4 = o - s * 504;
        int p  = p4 * 4;
        int i = (int)((127.0f - sqrtf(16129.0f - 8.0f * (float)p)) * 0.5f);
        while (((i + 1) * (126 - i)) >> 1 <= p) ++i;
        while ((i * (127 - i)) >> 1 > p) --i;
        int j = i + 1 + (p - ((i * (127 - i)) >> 1));

        const float* Gs = G + s * 64 * GSTR;
        float4 ov;
        ov.x = Gs[i * GSTR + j]; if (++j == NF) { ++i; j = i + 1; }
        ov.y = Gs[i * GSTR + j]; if (++j == NF) { ++i; j = i + 1; }
        ov.z = Gs[i * GSTR + j]; if (++j == NF) { ++i; j = i + 1; }
        ov.w = Gs[i * GSTR + j];
        *(float4*)(out + ((size_t)blockIdx.x * 2 + s) * NPAIR + p) = ov;
    }
}

extern "C" void kernel_launch(void* const* d_in, const int* in_sizes, int n_in,
                              void* d_out, int out_size)
{
    const float* in  = (const float*)d_in[0];
    float*       out = (float*)d_out;
    int nb = in_sizes[0] / (NF * ND);      // 16384
    cudaFuncSetAttribute(gram_hmma,
                         cudaFuncAttributeMaxDynamicSharedMemorySize, SMEM_TOTAL);
    gram_hmma<<<nb / 2, 128, SMEM_TOTAL>>>(in, out);
}

// round 6
// speedup vs baseline: 3.3220x; 1.3023x over previous
#include <cuda_runtime.h>
#include <stdint.h>

#define NF 64
#define NPAIR 2016
#define AROWB 144                  // bytes per field row: 64B hi | 64B lo | 16B pad
#define A_BYTES (2 * 64 * AROWB)   // 18432

__device__ __forceinline__ uint32_t s2u(const void* p) {
    return (uint32_t)__cvta_generic_to_shared(p);
}

__device__ __forceinline__ void mma16816(float* c, const uint32_t* a,
                                         uint32_t b0, uint32_t b1) {
    asm volatile(
        "mma.sync.aligned.m16n8k16.row.col.f32.bf16.bf16.f32 "
        "{%0,%1,%2,%3}, {%4,%5,%6,%7}, {%8,%9}, {%0,%1,%2,%3};"
        : "+f"(c[0]), "+f"(c[1]), "+f"(c[2]), "+f"(c[3])
        : "r"(a[0]), "r"(a[1]), "r"(a[2]), "r"(a[3]), "r"(b0), "r"(b1));
}

#define LDSM4(r, addr) \
    asm volatile("ldmatrix.sync.aligned.m8n8.x4.shared.b16 {%0,%1,%2,%3}, [%4];" \
        : "=r"((r)[0]), "=r"((r)[1]), "=r"((r)[2]), "=r"((r)[3]) : "r"(addr))

// Job: sample S, rows [R0,R0+16), n-tiles TMIN..7. Fragments register-cached:
// A hi/lo loaded once (4 LDSM.x4), B hi/lo once per tile (2 LDSM.x4 covering k0-31).
// Results go straight into the packed upper-triangle stage (guarded scalar STS).
template<int S, int R0, int TMIN>
__device__ __forceinline__ void job(uint32_t smA, float* stg, int lane)
{
    const uint32_t pA = smA + (uint32_t)((S * 64 + R0 + (lane & 15)) * AROWB)
                            + (uint32_t)((lane >> 4) << 4);
    const uint32_t pB = smA + (uint32_t)((S * 64 + (lane & 7)) * AROWB)
                            + (uint32_t)((lane >> 3) << 4);
    uint32_t Ah[8], Al[8];
    LDSM4(Ah,     pA);        // hi k0-15
    LDSM4(Ah + 4, pA + 32);   // hi k16-31
    LDSM4(Al,     pA + 64);   // lo k0-15
    LDSM4(Al + 4, pA + 96);   // lo k16-31

    const int r0 = R0 + (lane >> 2);
    const int r1 = r0 + 8;
    const int base0 = ((r0 * (127 - r0)) >> 1) - r0 - 1;   // p = base + j
    const int base1 = ((r1 * (127 - r1)) >> 1) - r1 - 1;
    float* st = stg + S * NPAIR;

    #pragma unroll
    for (int t = TMIN; t < 8; ++t) {
        uint32_t Bh[4], Bl[4];
        LDSM4(Bh, pB + (uint32_t)(t * 8 * AROWB));
        LDSM4(Bl, pB + (uint32_t)(t * 8 * AROWB) + 64);
        float c[4] = {0.f, 0.f, 0.f, 0.f};
        mma16816(c, Ah,     Bh[0], Bh[1]);   // hi.hi k0-15
        mma16816(c, Ah + 4, Bh[2], Bh[3]);   // hi.hi k16-31
        mma16816(c, Ah,     Bl[0], Bl[1]);   // hi.lo
        mma16816(c, Ah + 4, Bl[2], Bl[3]);
        mma16816(c, Al,     Bh[0], Bh[1]);   // lo.hi
        mma16816(c, Al + 4, Bh[2], Bh[3]);

        const int col = 8 * t + 2 * (lane & 3);
        if (col     > r0) st[base0 + col]     = c[0];
        if (col + 1 > r0) st[base0 + col + 1] = c[1];
        if (col     > r1) st[base1 + col]     = c[2];
        if (col + 1 > r1) st[base1 + col + 1] = c[3];
    }
}

__global__ __launch_bounds__(128, 4)
void gram_hmma2(const float* __restrict__ in, float* __restrict__ out)
{
    __shared__ __align__(16) uint8_t smem[A_BYTES];
    __shared__ __align__(16) float stg[2 * NPAIR];

    const int tid  = threadIdx.x;
    const int w    = tid >> 5;
    const int lane = tid & 31;
    const uint32_t smA = s2u(smem);

    // ---- Phase 1: load 2 samples, split fp32 -> hi/lo bf16, field-major tile
    {
        const float4* src = (const float4*)(in + (size_t)blockIdx.x * 4096);
        #pragma unroll
        for (int k = 0; k < 8; ++k) {
            int idx = tid + k * 128;            // 1024 float4 (2 samples)
            float4 v = src[idx];
            int row = idx >> 3;                 // sample*64 + field
            int dq  = idx & 7;                  // d0 = 4*dq
            uint32_t hA, hB, lA, lB;
            asm("cvt.rn.bf16x2.f32 %0, %1, %2;" : "=r"(hA) : "f"(v.y), "f"(v.x));
            asm("cvt.rn.bf16x2.f32 %0, %1, %2;" : "=r"(hB) : "f"(v.w), "f"(v.z));
            float r0 = v.x - __uint_as_float(hA << 16);
            float r1 = v.y - __uint_as_float(hA & 0xFFFF0000u);
            float r2 = v.z - __uint_as_float(hB << 16);
            float r3 = v.w - __uint_as_float(hB & 0xFFFF0000u);
            asm("cvt.rn.bf16x2.f32 %0, %1, %2;" : "=r"(lA) : "f"(r1), "f"(r0));
            asm("cvt.rn.bf16x2.f32 %0, %1, %2;" : "=r"(lB) : "f"(r3), "f"(r2));
            uint8_t* base = smem + row * AROWB + dq * 8;
            *(uint2*)base        = make_uint2(hA, hB);   // hi
            *(uint2*)(base + 64) = make_uint2(lA, lB);   // lo
        }
    }
    __syncthreads();

    // ---- Phase 2: tensor-core gram, triangle-balanced, staged packed
    switch (w) {
    case 0:  job<0,  0, 0>(smA, stg, lane); job<1, 48, 6>(smA, stg, lane); break;
    case 1:  job<0, 16, 2>(smA, stg, lane); job<1, 32, 4>(smA, stg, lane); break;
    case 2:  job<0, 32, 4>(smA, stg, lane); job<1, 16, 2>(smA, stg, lane); break;
    default: job<0, 48, 6>(smA, stg, lane); job<1,  0, 0>(smA, stg, lane); break;
    }
    __syncthreads();

    // ---- Phase 3: sequential float4 copy-out of packed triangles
    #pragma unroll
    for (int q = 0; q < 8; ++q) {
        int o = tid + q * 128;
        if (o < 1008) {
            int s  = o >= 504;
            int p4 = o - s * 504;
            float4 v = *(const float4*)(stg + s * NPAIR + p4 * 4);
            *(float4*)(out + ((size_t)blockIdx.x * 2 + s) * NPAIR + p4 * 4) = v;
        }
    }
}

extern "C" void kernel_launch(void* const* d_in, const int* in_sizes, int n_in,
                              void* d_out, int out_size)
{
    const float* in  = (const float*)d_in[0];
    float*       out = (float*)d_out;
    int nb = in_sizes[0] / (NF * 32);      // 16384
    gram_hmma2<<<nb / 2, 128>>>(in, out);
}

// round 10
// speedup vs baseline: 3.4543x; 1.0398x over previous
#include <cuda_runtime.h>
#include <stdint.h>

#define NF 64
#define NPAIR 2016
#define AROWB 144                    // bytes per field row: 64B hi | 64B lo | 16B pad
#define SAMPLE_B (64 * AROWB)        // 9216 bytes per sample tile
#define A_BYTES (2 * SAMPLE_B)       // 18432

__device__ __forceinline__ uint32_t s2u(const void* p) {
    return (uint32_t)__cvta_generic_to_shared(p);
}

__device__ __forceinline__ void mma16816(float* c, const uint32_t* a,
                                         uint32_t b0, uint32_t b1) {
    asm volatile(
        "mma.sync.aligned.m16n8k16.row.col.f32.bf16.bf16.f32 "
        "{%0,%1,%2,%3}, {%4,%5,%6,%7}, {%8,%9}, {%0,%1,%2,%3};"
        : "+f"(c[0]), "+f"(c[1]), "+f"(c[2]), "+f"(c[3])
        : "r"(a[0]), "r"(a[1]), "r"(a[2]), "r"(a[3]), "r"(b0), "r"(b1));
}

#define LDSM4(r, addr) \
    asm volatile("ldmatrix.sync.aligned.m8n8.x4.shared.b16 {%0,%1,%2,%3}, [%4];" \
        : "=r"((r)[0]), "=r"((r)[1]), "=r"((r)[2]), "=r"((r)[3]) : "r"(addr))

// One row-strip [16R, 16R+16) of this warp's sample against register-resident B.
template<int R>
__device__ __forceinline__ void strip(uint32_t pA0,
                                      const uint32_t Bh[8][4],
                                      const uint32_t Bl[8][4],
                                      float* st, int lane)
{
    const uint32_t pA = pA0 + (uint32_t)(16 * R * AROWB);
    uint32_t Ah[8], Al[8];
    LDSM4(Ah,     pA);        // hi k0-15
    LDSM4(Ah + 4, pA + 32);   // hi k16-31
    LDSM4(Al,     pA + 64);   // lo k0-15
    LDSM4(Al + 4, pA + 96);   // lo k16-31

    const int r0 = 16 * R + (lane >> 2);
    const int r1 = r0 + 8;
    const int b0 = ((r0 * (127 - r0)) >> 1) - r0 - 1;   // packed: p = b + j
    const int b1 = ((r1 * (127 - r1)) >> 1) - r1 - 1;

    #pragma unroll
    for (int t = 2 * R; t < 8; ++t) {
        float c[4] = {0.f, 0.f, 0.f, 0.f};
        mma16816(c, Ah,     Bh[t][0], Bh[t][1]);   // hi.hi
        mma16816(c, Ah + 4, Bh[t][2], Bh[t][3]);
        mma16816(c, Ah,     Bl[t][0], Bl[t][1]);   // hi.lo
        mma16816(c, Ah + 4, Bl[t][2], Bl[t][3]);
        mma16816(c, Al,     Bh[t][0], Bh[t][1]);   // lo.hi
        mma16816(c, Al + 4, Bh[t][2], Bh[t][3]);

        const int c0 = 8 * t + 2 * (lane & 3);
        if (t == 2 * R) {                    // diagonal tile: row-half 0 guarded,
            if (c0     > r0) st[b0 + c0]     = c[0];   // row-half 1 all below diag
            if (c0 + 1 > r0) st[b0 + c0 + 1] = c[1];
        } else if (t == 2 * R + 1) {         // row-half 0 fully above, half 1 guarded
            st[b0 + c0]     = c[0];
            st[b0 + c0 + 1] = c[1];
            if (c0     > r1) st[b1 + c0]     = c[2];
            if (c0 + 1 > r1) st[b1 + c0 + 1] = c[3];
        } else {                             // fully above diagonal
            st[b0 + c0]     = c[0];
            st[b0 + c0 + 1] = c[1];
            st[b1 + c0]     = c[2];
            st[b1 + c0 + 1] = c[3];
        }
    }
}

__global__ __launch_bounds__(64, 6)
void gram_hmma3(const float* __restrict__ in, float* __restrict__ out)
{
    __shared__ __align__(16) uint8_t smem[A_BYTES];
    __shared__ __align__(16) float stg[2 * NPAIR];

    const int tid  = threadIdx.x;
    const int w    = tid >> 5;               // warp = sample
    const int lane = tid & 31;
    const uint32_t smA = s2u(smem);

    // ---- Phase 1: load 2 samples, split fp32 -> hi/lo bf16, field-major tile
    {
        const float4* src = (const float4*)(in + (size_t)blockIdx.x * 4096);
        #pragma unroll
        for (int k = 0; k < 16; ++k) {
            int idx = tid + k * 64;            // 1024 float4 (2 samples)
            float4 v = src[idx];
            int row = idx >> 3;                // sample*64 + field
            int dq  = idx & 7;                 // d0 = 4*dq
            uint32_t hA, hB, lA, lB;
            asm("cvt.rn.bf16x2.f32 %0, %1, %2;" : "=r"(hA) : "f"(v.y), "f"(v.x));
            asm("cvt.rn.bf16x2.f32 %0, %1, %2;" : "=r"(hB) : "f"(v.w), "f"(v.z));
            float r0 = v.x - __uint_as_float(hA << 16);
            float r1 = v.y - __uint_as_float(hA & 0xFFFF0000u);
            float r2 = v.z - __uint_as_float(hB << 16);
            float r3 = v.w - __uint_as_float(hB & 0xFFFF0000u);
            asm("cvt.rn.bf16x2.f32 %0, %1, %2;" : "=r"(lA) : "f"(r1), "f"(r0));
            asm("cvt.rn.bf16x2.f32 %0, %1, %2;" : "=r"(lB) : "f"(r3), "f"(r2));
            uint8_t* base = smem + row * AROWB + dq * 8;
            *(uint2*)base        = make_uint2(hA, hB);   // hi
            *(uint2*)(base + 64) = make_uint2(lA, lB);   // lo
        }
    }
    __syncthreads();

    // ---- Phase 2: per-warp sample gram; B register-resident, A streamed
    {
        const uint32_t base = smA + (uint32_t)(w * SAMPLE_B);
        const uint32_t pB = base + (uint32_t)((lane & 7) * AROWB)
                                 + (uint32_t)((lane >> 3) << 4);
        uint32_t Bh[8][4], Bl[8][4];
        #pragma unroll
        for (int t = 0; t < 8; ++t) {
            LDSM4(Bh[t], pB + (uint32_t)(t * 8 * AROWB));
            LDSM4(Bl[t], pB + (uint32_t)(t * 8 * AROWB) + 64);
        }

        const uint32_t pA0 = base + (uint32_t)((lane & 15) * AROWB)
                                  + (uint32_t)((lane >> 4) << 4);
        float* st = stg + w * NPAIR;
        strip<0>(pA0, Bh, Bl, st, lane);
        strip<1>(pA0, Bh, Bl, st, lane);
        strip<2>(pA0, Bh, Bl, st, lane);
        strip<3>(pA0, Bh, Bl, st, lane);
    }
    __syncthreads();

    // ---- Phase 3: sequential float4 copy-out of packed triangles
    #pragma unroll
    for (int q = 0; q < 16; ++q) {
        int o = tid + q * 64;
        if (o < 1008) {
            int s  = o >= 504;
            int p4 = o - s * 504;
            float4 v = *(const float4*)(stg + s * NPAIR + p4 * 4);
            *(float4*)(out + ((size_t)blockIdx.x * 2 + s) * NPAIR + p4 * 4) = v;
        }
    }
}

extern "C" void kernel_launch(void* const* d_in, const int* in_sizes, int n_in,
                              void* d_out, int out_size)
{
    const float* in  = (const float*)d_in[0];
    float*       out = (float*)d_out;
    int nb = in_sizes[0] / (NF * 32);      // 16384
    gram_hmma3<<<nb / 2, 64>>>(in, out);
}

// round 11
// speedup vs baseline: 3.4774x; 1.0067x over previous
#include <cuda_runtime.h>
#include <stdint.h>

#define NF 64
#define NPAIR 2016
#define AROWB 144                    // bytes per field row: 64B hi | 64B lo | 16B pad
#define SAMPLE_B (64 * AROWB)        // 9216 bytes per sample tile
#define A_BYTES (2 * SAMPLE_B)       // 18432
#define STGW 896                     // per-warp stage floats (max strip = 888)

__device__ __forceinline__ uint32_t s2u(const void* p) {
    return (uint32_t)__cvta_generic_to_shared(p);
}

__device__ __forceinline__ void mma16816(float* c, const uint32_t* a,
                                         uint32_t b0, uint32_t b1) {
    asm volatile(
        "mma.sync.aligned.m16n8k16.row.col.f32.bf16.bf16.f32 "
        "{%0,%1,%2,%3}, {%4,%5,%6,%7}, {%8,%9}, {%0,%1,%2,%3};"
        : "+f"(c[0]), "+f"(c[1]), "+f"(c[2]), "+f"(c[3])
        : "r"(a[0]), "r"(a[1]), "r"(a[2]), "r"(a[3]), "r"(b0), "r"(b1));
}

#define LDSM4(r, addr) \
    asm volatile("ldmatrix.sync.aligned.m8n8.x4.shared.b16 {%0,%1,%2,%3}, [%4];" \
        : "=r"((r)[0]), "=r"((r)[1]), "=r"((r)[2]), "=r"((r)[3]) : "r"(addr))

// Strip R: rows [16R,16R+16) vs register-resident B; packed region
// [S0, S0+SZ) staged in the warp buffer then copied out immediately.
template<int R>
__device__ __forceinline__ void strip(uint32_t pA0,
                                      const uint32_t Bh[8][4],
                                      const uint32_t Bl[8][4],
                                      float* st, float* outp, int lane)
{
    constexpr int S0 = (16 * R * (127 - 16 * R)) / 2;   // 0, 888, 1520, 1896
    constexpr int SZ = 888 - 256 * R;                   // 888, 632, 376, 120

    const uint32_t pA = pA0 + (uint32_t)(16 * R * AROWB);
    uint32_t Ah[8], Al[8];
    LDSM4(Ah,     pA);        // hi k0-15
    LDSM4(Ah + 4, pA + 32);   // hi k16-31
    LDSM4(Al,     pA + 64);   // lo k0-15
    LDSM4(Al + 4, pA + 96);   // lo k16-31

    const int r0 = 16 * R + (lane >> 2);
    const int r1 = r0 + 8;
    const int b0 = ((r0 * (127 - r0)) >> 1) - r0 - 1 - S0;   // strip-relative
    const int b1 = ((r1 * (127 - r1)) >> 1) - r1 - 1 - S0;

    #pragma unroll
    for (int t = 2 * R; t < 8; ++t) {
        float c[4] = {0.f, 0.f, 0.f, 0.f};
        mma16816(c, Ah,     Bh[t][0], Bh[t][1]);   // hi.hi
        mma16816(c, Ah + 4, Bh[t][2], Bh[t][3]);
        mma16816(c, Ah,     Bl[t][0], Bl[t][1]);   // hi.lo
        mma16816(c, Ah + 4, Bl[t][2], Bl[t][3]);
        mma16816(c, Al,     Bh[t][0], Bh[t][1]);   // lo.hi
        mma16816(c, Al + 4, Bh[t][2], Bh[t][3]);

        const int c0 = 8 * t + 2 * (lane & 3);
        if (t == 2 * R) {                    // diagonal tile: half 0 guarded
            if (c0     > r0) st[b0 + c0]     = c[0];
            if (c0 + 1 > r0) st[b0 + c0 + 1] = c[1];
        } else if (t == 2 * R + 1) {         // half 0 above diag, half 1 guarded
            st[b0 + c0]     = c[0];
            st[b0 + c0 + 1] = c[1];
            if (c0     > r1) st[b1 + c0]     = c[2];
            if (c0 + 1 > r1) st[b1 + c0 + 1] = c[3];
        } else {                             // fully above diagonal
            st[b0 + c0]     = c[0];
            st[b0 + c0 + 1] = c[1];
            st[b1 + c0]     = c[2];
            st[b1 + c0 + 1] = c[3];
        }
    }
    __syncwarp();

    // immediate coalesced copy-out of this strip's packed region
    constexpr int QUADS = SZ / 4;            // 222, 158, 94, 30
    #pragma unroll
    for (int qb = 0; qb < (QUADS + 31) / 32; ++qb) {
        int q = lane + qb * 32;
        if (QUADS % 32 == 0 || q < QUADS) {
            float4 v = *(const float4*)(st + q * 4);
            *(float4*)(outp + S0 + q * 4) = v;
        }
    }
    __syncwarp();                            // stage reusable for next strip
}

__global__ __launch_bounds__(64, 8)
void gram_hmma4(const float* __restrict__ in, float* __restrict__ out)
{
    __shared__ __align__(16) uint8_t smem[A_BYTES];
    __shared__ __align__(16) float stg[2][STGW];

    const int tid  = threadIdx.x;
    const int w    = tid >> 5;               // warp = sample
    const int lane = tid & 31;

    uint8_t* tile = smem + w * SAMPLE_B;
    float*   outp = out + ((size_t)blockIdx.x * 2 + w) * NPAIR;

    // ---- Phase 1 (warp-local): load own sample, split fp32 -> hi/lo bf16
    {
        const float4* src = (const float4*)(in + ((size_t)blockIdx.x * 2 + w) * 2048);
        #pragma unroll
        for (int k = 0; k < 16; ++k) {
            int idx = lane + k * 32;           // 512 float4 (one sample)
            float4 v = src[idx];
            int row = idx >> 3;                // field
            int dq  = idx & 7;                 // d0 = 4*dq
            uint32_t hA, hB, lA, lB;
            asm("cvt.rn.bf16x2.f32 %0, %1, %2;" : "=r"(hA) : "f"(v.y), "f"(v.x));
            asm("cvt.rn.bf16x2.f32 %0, %1, %2;" : "=r"(hB) : "f"(v.w), "f"(v.z));
            float r0 = v.x - __uint_as_float(hA << 16);
            float r1 = v.y - __uint_as_float(hA & 0xFFFF0000u);
            float r2 = v.z - __uint_as_float(hB << 16);
            float r3 = v.w - __uint_as_float(hB & 0xFFFF0000u);
            asm("cvt.rn.bf16x2.f32 %0, %1, %2;" : "=r"(lA) : "f"(r1), "f"(r0));
            asm("cvt.rn.bf16x2.f32 %0, %1, %2;" : "=r"(lB) : "f"(r3), "f"(r2));
            uint8_t* base = tile + row * AROWB + dq * 8;
            *(uint2*)base        = make_uint2(hA, hB);   // hi
            *(uint2*)(base + 64) = make_uint2(lA, lB);   // lo
        }
    }
    __syncwarp();

    // ---- Phase 2: B register-resident, stream A strips, per-strip copy-out
    {
        const uint32_t base = s2u(tile);
        const uint32_t pB = base + (uint32_t)((lane & 7) * AROWB)
                                 + (uint32_t)((lane >> 3) << 4);
        uint32_t Bh[8][4], Bl[8][4];
        #pragma unroll
        for (int t = 0; t < 8; ++t) {
            LDSM4(Bh[t], pB + (uint32_t)(t * 8 * AROWB));
            LDSM4(Bl[t], pB + (uint32_t)(t * 8 * AROWB) + 64);
        }

        const uint32_t pA0 = base + (uint32_t)((lane & 15) * AROWB)
                                  + (uint32_t)((lane >> 4) << 4);
        float* st = stg[w];
        strip<0>(pA0, Bh, Bl, st, outp, lane);
        strip<1>(pA0, Bh, Bl, st, outp, lane);
        strip<2>(pA0, Bh, Bl, st, outp, lane);
        strip<3>(pA0, Bh, Bl, st, outp, lane);
    }
}

extern "C" void kernel_launch(void* const* d_in, const int* in_sizes, int n_in,
                              void* d_out, int out_size)
{
    const float* in  = (const float*)d_in[0];
    float*       out = (float*)d_out;
    int nb = in_sizes[0] / (NF * 32);      // 16384
    gram_hmma4<<<nb / 2, 64>>>(in, out);
}

// round 12
// speedup vs baseline: 3.5325x; 1.0158x over previous
#include <cuda_runtime.h>
#include <stdint.h>

#define NF 64
#define NPAIR 2016
#define AROWB 144                    // bytes per field row: 64B hi | 64B lo | 16B pad
#define SAMPLE_B (64 * AROWB)        // 9216 bytes per sample tile
#define A_BYTES (2 * SAMPLE_B)       // 18432
#define STGW 896                     // per-warp stage floats (max strip = 888)

__device__ __forceinline__ uint32_t s2u(const void* p) {
    return (uint32_t)__cvta_generic_to_shared(p);
}

__device__ __forceinline__ void mma4(float* c,
                                     uint32_t a0, uint32_t a1, uint32_t a2, uint32_t a3,
                                     uint32_t b0, uint32_t b1) {
    asm volatile(
        "mma.sync.aligned.m16n8k16.row.col.f32.bf16.bf16.f32 "
        "{%0,%1,%2,%3}, {%4,%5,%6,%7}, {%8,%9}, {%0,%1,%2,%3};"
        : "+f"(c[0]), "+f"(c[1]), "+f"(c[2]), "+f"(c[3])
        : "r"(a0), "r"(a1), "r"(a2), "r"(a3), "r"(b0), "r"(b1));
}

#define LDSM4(r, addr) \
    asm volatile("ldmatrix.sync.aligned.m8n8.x4.shared.b16 {%0,%1,%2,%3}, [%4];" \
        : "=r"((r)[0]), "=r"((r)[1]), "=r"((r)[2]), "=r"((r)[3]) : "r"(addr))

// Strip R: rows [16R,16R+16). A fragments are reused B-tile registers
// (tiles 2R and 2R+1) -- no A-side ldmatrix at all.
template<int R>
__device__ __forceinline__ void strip(const uint32_t Bh[8][4],
                                      const uint32_t Bl[8][4],
                                      float* st, float* outp, int lane)
{
    constexpr int S0 = (16 * R * (127 - 16 * R)) / 2;   // 0, 888, 1520, 1896
    constexpr int SZ = 888 - 256 * R;                   // 888, 632, 376, 120

    const int r0 = 16 * R + (lane >> 2);
    const int r1 = r0 + 8;
    const int b0 = ((r0 * (127 - r0)) >> 1) - r0 - 1 - S0;   // strip-relative
    const int b1 = ((r1 * (127 - r1)) >> 1) - r1 - 1 - S0;

    #pragma unroll
    for (int t = 2 * R; t < 8; ++t) {
        float c[4] = {0.f, 0.f, 0.f, 0.f};
        // hi.hi
        mma4(c, Bh[2*R][0], Bh[2*R+1][0], Bh[2*R][1], Bh[2*R+1][1], Bh[t][0], Bh[t][1]);
        mma4(c, Bh[2*R][2], Bh[2*R+1][2], Bh[2*R][3], Bh[2*R+1][3], Bh[t][2], Bh[t][3]);
        // hi.lo
        mma4(c, Bh[2*R][0], Bh[2*R+1][0], Bh[2*R][1], Bh[2*R+1][1], Bl[t][0], Bl[t][1]);
        mma4(c, Bh[2*R][2], Bh[2*R+1][2], Bh[2*R][3], Bh[2*R+1][3], Bl[t][2], Bl[t][3]);
        // lo.hi
        mma4(c, Bl[2*R][0], Bl[2*R+1][0], Bl[2*R][1], Bl[2*R+1][1], Bh[t][0], Bh[t][1]);
        mma4(c, Bl[2*R][2], Bl[2*R+1][2], Bl[2*R][3], Bl[2*R+1][3], Bh[t][2], Bh[t][3]);

        const int c0 = 8 * t + 2 * (lane & 3);
        if (t == 2 * R) {                    // diagonal tile: half 0 guarded
            if (c0     > r0) st[b0 + c0]     = c[0];
            if (c0 + 1 > r0) st[b0 + c0 + 1] = c[1];
        } else if (t == 2 * R + 1) {         // half 0 above diag, half 1 guarded
            st[b0 + c0]     = c[0];
            st[b0 + c0 + 1] = c[1];
            if (c0     > r1) st[b1 + c0]     = c[2];
            if (c0 + 1 > r1) st[b1 + c0 + 1] = c[3];
        } else {                             // fully above diagonal
            st[b0 + c0]     = c[0];
            st[b0 + c0 + 1] = c[1];
            st[b1 + c0]     = c[2];
            st[b1 + c0 + 1] = c[3];
        }
    }
    __syncwarp();

    // immediate coalesced copy-out of this strip's packed region
    constexpr int QUADS = SZ / 4;            // 222, 158, 94, 30
    #pragma unroll
    for (int qb = 0; qb < (QUADS + 31) / 32; ++qb) {
        int q = lane + qb * 32;
        if (QUADS % 32 == 0 || q < QUADS) {
            float4 v = *(const float4*)(st + q * 4);
            *(float4*)(outp + S0 + q * 4) = v;
        }
    }
    __syncwarp();                            // stage reusable for next strip
}

__global__ __launch_bounds__(64, 9)
void gram_hmma5(const float* __restrict__ in, float* __restrict__ out)
{
    __shared__ __align__(16) uint8_t smem[A_BYTES];
    __shared__ __align__(16) float stg[2][STGW];

    const int tid  = threadIdx.x;
    const int w    = tid >> 5;               // warp = sample
    const int lane = tid & 31;

    uint8_t* tile = smem + w * SAMPLE_B;
    float*   outp = out + ((size_t)blockIdx.x * 2 + w) * NPAIR;

    // ---- Phase 1 (warp-local): load own sample, split fp32 -> hi/lo bf16
    {
        const float4* src = (const float4*)(in + ((size_t)blockIdx.x * 2 + w) * 2048);
        #pragma unroll
        for (int k = 0; k < 16; ++k) {
            int idx = lane + k * 32;           // 512 float4 (one sample)
            float4 v = src[idx];
            int row = idx >> 3;                // field
            int dq  = idx & 7;                 // d0 = 4*dq
            uint32_t hA, hB, lA, lB;
            asm("cvt.rn.bf16x2.f32 %0, %1, %2;" : "=r"(hA) : "f"(v.y), "f"(v.x));
            asm("cvt.rn.bf16x2.f32 %0, %1, %2;" : "=r"(hB) : "f"(v.w), "f"(v.z));
            float r0 = v.x - __uint_as_float(hA << 16);
            float r1 = v.y - __uint_as_float(hA & 0xFFFF0000u);
            float r2 = v.z - __uint_as_float(hB << 16);
            float r3 = v.w - __uint_as_float(hB & 0xFFFF0000u);
            asm("cvt.rn.bf16x2.f32 %0, %1, %2;" : "=r"(lA) : "f"(r1), "f"(r0));
            asm("cvt.rn.bf16x2.f32 %0, %1, %2;" : "=r"(lB) : "f"(r3), "f"(r2));
            uint8_t* base = tile + row * AROWB + dq * 8;
            *(uint2*)base        = make_uint2(hA, hB);   // hi
            *(uint2*)(base + 64) = make_uint2(lA, lB);   // lo
        }
    }
    __syncwarp();

    // ---- Phase 2: load B tiles once (they double as A fragments), stream strips
    {
        const uint32_t base = s2u(tile);
        const uint32_t pB = base + (uint32_t)((lane & 7) * AROWB)
                                 + (uint32_t)((lane >> 3) << 4);
        uint32_t Bh[8][4], Bl[8][4];
        #pragma unroll
        for (int t = 0; t < 8; ++t) {
            LDSM4(Bh[t], pB + (uint32_t)(t * 8 * AROWB));
            LDSM4(Bl[t], pB + (uint32_t)(t * 8 * AROWB) + 64);
        }

        float* st = stg[w];
        strip<0>(Bh, Bl, st, outp, lane);
        strip<1>(Bh, Bl, st, outp, lane);
        strip<2>(Bh, Bl, st, outp, lane);
        strip<3>(Bh, Bl, st, outp, lane);
    }
}

extern "C" void kernel_launch(void* const* d_in, const int* in_sizes, int n_in,
                              void* d_out, int out_size)
{
    const float* in  = (const float*)d_in[0];
    float*       out = (float*)d_out;
    int nb = in_sizes[0] / (NF * 32);      // 16384
    gram_hmma5<<<nb / 2, 64>>>(in, out);
}

// round 13
// speedup vs baseline: 4.0506x; 1.1467x over previous
#include <cuda_runtime.h>
#include <stdint.h>

#define NF 64
#define NPAIR 2016
#define AROWB 144                    // bytes per field row: 64B hi | 64B lo | 16B pad
#define SAMPLE_B (64 * AROWB)        // 9216 bytes per sample tile
#define A_BYTES (2 * SAMPLE_B)       // 18432 (stage aliases the tile after LDSM)

__device__ __forceinline__ uint32_t s2u(const void* p) {
    return (uint32_t)__cvta_generic_to_shared(p);
}

__device__ __forceinline__ void mma4(float* c,
                                     uint32_t a0, uint32_t a1, uint32_t a2, uint32_t a3,
                                     uint32_t b0, uint32_t b1) {
    asm volatile(
        "mma.sync.aligned.m16n8k16.row.col.f32.bf16.bf16.f32 "
        "{%0,%1,%2,%3}, {%4,%5,%6,%7}, {%8,%9}, {%0,%1,%2,%3};"
        : "+f"(c[0]), "+f"(c[1]), "+f"(c[2]), "+f"(c[3])
        : "r"(a0), "r"(a1), "r"(a2), "r"(a3), "r"(b0), "r"(b1));
}

#define LDSM4(r, addr) \
    asm volatile("ldmatrix.sync.aligned.m8n8.x4.shared.b16 {%0,%1,%2,%3}, [%4];" \
        : "=r"((r)[0]), "=r"((r)[1]), "=r"((r)[2]), "=r"((r)[3]) : "r"(addr))

// Strip R: rows [16R,16R+16). A fragments are reused B-tile registers
// (tiles 2R and 2R+1). Packed region [S0,S0+SZ) staged (aliasing the dead
// operand tile) then copied out coalesced.
template<int R>
__device__ __forceinline__ void strip(const uint32_t Bh[8][4],
                                      const uint32_t Bl[8][4],
                                      float* st, float* outp, int lane)
{
    constexpr int S0 = (16 * R * (127 - 16 * R)) / 2;   // 0, 888, 1520, 1896
    constexpr int SZ = 888 - 256 * R;                   // 888, 632, 376, 120

    const int r0 = 16 * R + (lane >> 2);
    const int r1 = r0 + 8;
    const int b0 = ((r0 * (127 - r0)) >> 1) - r0 - 1 - S0;   // strip-relative
    const int b1 = ((r1 * (127 - r1)) >> 1) - r1 - 1 - S0;

    #pragma unroll
    for (int t = 2 * R; t < 8; ++t) {
        float c[4] = {0.f, 0.f, 0.f, 0.f};
        // hi.hi
        mma4(c, Bh[2*R][0], Bh[2*R+1][0], Bh[2*R][1], Bh[2*R+1][1], Bh[t][0], Bh[t][1]);
        mma4(c, Bh[2*R][2], Bh[2*R+1][2], Bh[2*R][3], Bh[2*R+1][3], Bh[t][2], Bh[t][3]);
        // hi.lo
        mma4(c, Bh[2*R][0], Bh[2*R+1][0], Bh[2*R][1], Bh[2*R+1][1], Bl[t][0], Bl[t][1]);
        mma4(c, Bh[2*R][2], Bh[2*R+1][2], Bh[2*R][3], Bh[2*R+1][3], Bl[t][2], Bl[t][3]);
        // lo.hi
        mma4(c, Bl[2*R][0], Bl[2*R+1][0], Bl[2*R][1], Bl[2*R+1][1], Bh[t][0], Bh[t][1]);
        mma4(c, Bl[2*R][2], Bl[2*R+1][2], Bl[2*R][3], Bl[2*R+1][3], Bh[t][2], Bh[t][3]);

        const int c0 = 8 * t + 2 * (lane & 3);
        if (t == 2 * R) {                    // diagonal tile: half 0 guarded
            if (c0     > r0) st[b0 + c0]     = c[0];
            if (c0 + 1 > r0) st[b0 + c0 + 1] = c[1];
        } else if (t == 2 * R + 1) {         // half 0 above diag, half 1 guarded
            st[b0 + c0]     = c[0];
            st[b0 + c0 + 1] = c[1];
            if (c0     > r1) st[b1 + c0]     = c[2];
            if (c0 + 1 > r1) st[b1 + c0 + 1] = c[3];
        } else {                             // fully above diagonal
            st[b0 + c0]     = c[0];
            st[b0 + c0 + 1] = c[1];
            st[b1 + c0]     = c[2];
            st[b1 + c0 + 1] = c[3];
        }
    }
    __syncwarp();

    // immediate coalesced copy-out of this strip's packed region
    constexpr int QUADS = SZ / 4;            // 222, 158, 94, 30
    #pragma unroll
    for (int qb = 0; qb < (QUADS + 31) / 32; ++qb) {
        int q = lane + qb * 32;
        if (QUADS % 32 == 0 || q < QUADS) {
            float4 v = *(const float4*)(st + q * 4);
            *(float4*)(outp + S0 + q * 4) = v;
        }
    }
    __syncwarp();                            // stage reusable for next strip
}

__global__ __launch_bounds__(64, 10)
void gram_hmma6(const float* __restrict__ in, float* __restrict__ out)
{
    __shared__ __align__(16) uint8_t smem[A_BYTES];

    const int tid  = threadIdx.x;
    const int w    = tid >> 5;               // warp = sample
    const int lane = tid & 31;

    uint8_t* tile = smem + w * SAMPLE_B;
    float*   outp = out + ((size_t)blockIdx.x * 2 + w) * NPAIR;

    // ---- Phase 1 (warp-local): load own sample, split fp32 -> hi/lo bf16
    {
        const float4* src = (const float4*)(in + ((size_t)blockIdx.x * 2 + w) * 2048);
        #pragma unroll
        for (int k = 0; k < 16; ++k) {
            int idx = lane + k * 32;           // 512 float4 (one sample)
            float4 v = src[idx];
            int row = idx >> 3;                // field
            int dq  = idx & 7;                 // d0 = 4*dq
            uint32_t hA, hB, lA, lB;
            asm("cvt.rn.bf16x2.f32 %0, %1, %2;" : "=r"(hA) : "f"(v.y), "f"(v.x));
            asm("cvt.rn.bf16x2.f32 %0, %1, %2;" : "=r"(hB) : "f"(v.w), "f"(v.z));
            float r0 = v.x - __uint_as_float(hA << 16);
            float r1 = v.y - __uint_as_float(hA & 0xFFFF0000u);
            float r2 = v.z - __uint_as_float(hB << 16);
            float r3 = v.w - __uint_as_float(hB & 0xFFFF0000u);
            asm("cvt.rn.bf16x2.f32 %0, %1, %2;" : "=r"(lA) : "f"(r1), "f"(r0));
            asm("cvt.rn.bf16x2.f32 %0, %1, %2;" : "=r"(lB) : "f"(r3), "f"(r2));
            uint8_t* base = tile + row * AROWB + dq * 8;
            *(uint2*)base        = make_uint2(hA, hB);   // hi
            *(uint2*)(base + 64) = make_uint2(lA, lB);   // lo
        }
    }
    __syncwarp();

    // ---- Phase 2: load all B tiles once (they double as A fragments)
    {
        const uint32_t base = s2u(tile);
        const uint32_t pB = base + (uint32_t)((lane & 7) * AROWB)
                                 + (uint32_t)((lane >> 3) << 4);
        uint32_t Bh[8][4], Bl[8][4];
        #pragma unroll
        for (int t = 0; t < 8; ++t) {
            LDSM4(Bh[t], pB + (uint32_t)(t * 8 * AROWB));
            LDSM4(Bl[t], pB + (uint32_t)(t * 8 * AROWB) + 64);
        }
        __syncwarp();                 // all LDSM done -> tile smem is dead

        float* st = (float*)tile;     // stage aliases the dead operand tile
        strip<0>(Bh, Bl, st, outp, lane);
        strip<1>(Bh, Bl, st, outp, lane);
        strip<2>(Bh, Bl, st, outp, lane);
        strip<3>(Bh, Bl, st, outp, lane);
    }
}

extern "C" void kernel_launch(void* const* d_in, const int* in_sizes, int n_in,
                              void* d_out, int out_size)
{
    const float* in  = (const float*)d_in[0];
    float*       out = (float*)d_out;
    int nb = in_sizes[0] / (NF * 32);      // 16384
    gram_hmma6<<<nb / 2, 64>>>(in, out);
}

// round 14
// speedup vs baseline: 4.1977x; 1.0363x over previous
#include <cuda_runtime.h>
#include <stdint.h>

#define NF 64
#define NPAIR 2016
#define STGW 896                     // per-warp stage floats (max strip = 888)

__device__ __forceinline__ void mma4(float* c,
                                     uint32_t a0, uint32_t a1, uint32_t a2, uint32_t a3,
                                     uint32_t b0, uint32_t b1) {
    asm volatile(
        "mma.sync.aligned.m16n8k16.row.col.f32.bf16.bf16.f32 "
        "{%0,%1,%2,%3}, {%4,%5,%6,%7}, {%8,%9}, {%0,%1,%2,%3};"
        : "+f"(c[0]), "+f"(c[1]), "+f"(c[2]), "+f"(c[3])
        : "r"(a0), "r"(a1), "r"(a2), "r"(a3), "r"(b0), "r"(b1));
}

// Strip R: rows [16R,16R+16). A fragments are reused B-tile registers
// (tiles 2R and 2R+1). Packed region [S0,S0+SZ) staged then copied out.
template<int R>
__device__ __forceinline__ void strip(const uint32_t Bh[8][4],
                                      const uint32_t Bl[8][4],
                                      float* st, float* outp, int lane)
{
    constexpr int S0 = (16 * R * (127 - 16 * R)) / 2;   // 0, 888, 1520, 1896
    constexpr int SZ = 888 - 256 * R;                   // 888, 632, 376, 120

    const int r0 = 16 * R + (lane >> 2);
    const int r1 = r0 + 8;
    const int b0 = ((r0 * (127 - r0)) >> 1) - r0 - 1 - S0;   // strip-relative
    const int b1 = ((r1 * (127 - r1)) >> 1) - r1 - 1 - S0;

    #pragma unroll
    for (int t = 2 * R; t < 8; ++t) {
        float c[4] = {0.f, 0.f, 0.f, 0.f};
        // hi.hi
        mma4(c, Bh[2*R][0], Bh[2*R+1][0], Bh[2*R][1], Bh[2*R+1][1], Bh[t][0], Bh[t][1]);
        mma4(c, Bh[2*R][2], Bh[2*R+1][2], Bh[2*R][3], Bh[2*R+1][3], Bh[t][2], Bh[t][3]);
        // hi.lo
        mma4(c, Bh[2*R][0], Bh[2*R+1][0], Bh[2*R][1], Bh[2*R+1][1], Bl[t][0], Bl[t][1]);
        mma4(c, Bh[2*R][2], Bh[2*R+1][2], Bh[2*R][3], Bh[2*R+1][3], Bl[t][2], Bl[t][3]);
        // lo.hi
        mma4(c, Bl[2*R][0], Bl[2*R+1][0], Bl[2*R][1], Bl[2*R+1][1], Bh[t][0], Bh[t][1]);
        mma4(c, Bl[2*R][2], Bl[2*R+1][2], Bl[2*R][3], Bl[2*R+1][3], Bh[t][2], Bh[t][3]);

        const int c0 = 8 * t + 2 * (lane & 3);
        if (t == 2 * R) {                    // diagonal tile: half 0 guarded
            if (c0     > r0) st[b0 + c0]     = c[0];
            if (c0 + 1 > r0) st[b0 + c0 + 1] = c[1];
        } else if (t == 2 * R + 1) {         // half 0 above diag, half 1 guarded
            st[b0 + c0]     = c[0];
            st[b0 + c0 + 1] = c[1];
            if (c0     > r1) st[b1 + c0]     = c[2];
            if (c0 + 1 > r1) st[b1 + c0 + 1] = c[3];
        } else {                             // fully above diagonal
            st[b0 + c0]     = c[0];
            st[b0 + c0 + 1] = c[1];
            st[b1 + c0]     = c[2];
            st[b1 + c0 + 1] = c[3];
        }
    }
    __syncwarp();

    // immediate coalesced copy-out of this strip's packed region
    constexpr int QUADS = SZ / 4;            // 222, 158, 94, 30
    #pragma unroll
    for (int qb = 0; qb < (QUADS + 31) / 32; ++qb) {
        int q = lane + qb * 32;
        if (QUADS % 32 == 0 || q < QUADS) {
            float4 v = *(const float4*)(st + q * 4);
            *(float4*)(outp + S0 + q * 4) = v;
        }
    }
    __syncwarp();                            // stage reusable for next strip
}

__global__ __launch_bounds__(64, 10)
void gram_hmma7(const float* __restrict__ in, float* __restrict__ out)
{
    __shared__ __align__(16) float stg[2][STGW];   // 7168 B

    const int tid  = threadIdx.x;
    const int w    = tid >> 5;               // warp = sample
    const int lane = tid & 31;

    float* outp = out + ((size_t)blockIdx.x * 2 + w) * NPAIR;

    // ---- Phase 1: build fragments DIRECTLY from gmem (no smem, no ldmatrix).
    // Bh[t][j] lane l = bf16x2 of (f = 8t + (l>>2), d = 8j + 2*(l&3), d+1).
    uint32_t Bh[8][4], Bl[8][4];
    {
        const float2* src = (const float2*)(in + ((size_t)blockIdx.x * 2 + w) * 2048);
        const int rbase = lane >> 2;          // row within 8-row tile
        const int koff  = lane & 3;           // float2 index within 8-dim group
        #pragma unroll
        for (int t = 0; t < 8; ++t) {
            const int f = 8 * t + rbase;
            #pragma unroll
            for (int j = 0; j < 4; ++j) {
                float2 v = src[f * 16 + 4 * j + koff];
                uint32_t hi, lo;
                asm("cvt.rn.bf16x2.f32 %0, %1, %2;" : "=r"(hi) : "f"(v.y), "f"(v.x));
                float q0 = v.x - __uint_as_float(hi << 16);
                float q1 = v.y - __uint_as_float(hi & 0xFFFF0000u);
                asm("cvt.rn.bf16x2.f32 %0, %1, %2;" : "=r"(lo) : "f"(q1), "f"(q0));
                Bh[t][j] = hi;
                Bl[t][j] = lo;
            }
        }
    }

    // ---- Phase 2: four row strips, A = reused B registers
    float* st = stg[w];
    strip<0>(Bh, Bl, st, outp, lane);
    strip<1>(Bh, Bl, st, outp, lane);
    strip<2>(Bh, Bl, st, outp, lane);
    strip<3>(Bh, Bl, st, outp, lane);
}

extern "C" void kernel_launch(void* const* d_in, const int* in_sizes, int n_in,
                              void* d_out, int out_size)
{
    const float* in  = (const float*)d_in[0];
    float*       out = (float*)d_out;
    int nb = in_sizes[0] / (NF * 32);      // 16384
    gram_hmma7<<<nb / 2, 64>>>(in, out);
}